// round 6
// baseline (speedup 1.0000x reference)
#include <cuda_runtime.h>
#include <cstdint>

#define L      2048
#define C_IN   16
#define GROUPS 4
#define NEG_INF -1000000000.0f
#define CAP    64          // smem staging capacity per list (gmem fallback above)

// Compressed sparsemax output: per (ch,row) a COLUMN-SORTED list of
// (col,val) nonzeros. Full-stride allocation => no overflow for any input.
// .x = column index as int bits, .y = prob value.
__device__ float2 g_list[(size_t)C_IN * L * L];
__device__ int    g_cnt[C_IN * L];

// ---------------------------------------------------------------------------
// Kernel 1: row-wise sparsemax (causal) -> sorted compressed nonzero list.
// One block (128 thr) per (channel,row); thread t owns cols [16t,16t+16).
// tau0 = rowmax-1 bounds the support; survivors of tau0 are compacted to smem
// (sorted), then WARP 0 ALONE finishes Michelot + the final gmem write.
// Only 3 block barriers total.
// ---------------------------------------------------------------------------
__global__ __launch_bounds__(128) void sparsemax_kernel(const float* __restrict__ scores)
{
    const int row  = blockIdx.x;
    const int ch   = blockIdx.y;
    const int tid  = threadIdx.x;
    const int lane = tid & 31;
    const int warp = tid >> 5;            // 4 warps
    const size_t base = ((size_t)ch * L + row) * (size_t)L;
    const int j0  = tid * 16;
    const int rem = row - j0;             // valid elements: x <= rem

    float z[16];
    if (rem >= 15) {
#pragma unroll
        for (int q = 0; q < 4; q++) {
            const float4 a = *reinterpret_cast<const float4*>(scores + base + j0 + 4 * q);
            z[4*q+0]=a.x; z[4*q+1]=a.y; z[4*q+2]=a.z; z[4*q+3]=a.w;
        }
    } else {
#pragma unroll
        for (int x = 0; x < 16; x++)
            z[x] = (x <= rem) ? scores[base + j0 + x] : NEG_INF;
    }

    __shared__ float  smax[4];
    __shared__ int    swtot[4];
    __shared__ float2 slist[2048];        // survivors of tau0 (capacity-proof)

    // ---- row max ----
    float m = z[0];
#pragma unroll
    for (int k = 1; k < 16; k++) m = fmaxf(m, z[k]);
#pragma unroll
    for (int o = 16; o > 0; o >>= 1) m = fmaxf(m, __shfl_xor_sync(0xffffffffu, m, o));
    if (lane == 0) smax[warp] = m;
    __syncthreads();                                           // (1)
    const float tau0 = fmaxf(fmaxf(smax[0], smax[1]), fmaxf(smax[2], smax[3])) - 1.0f;

    // ---- compact survivors of tau0 into smem, column-sorted ----
    unsigned nz = 0u;
#pragma unroll
    for (int x = 0; x < 16; x++)
        if (z[x] > tau0) nz |= (1u << x);
    const int tcnt = __popc(nz);

    int v = tcnt;                          // warp inclusive scan
#pragma unroll
    for (int o = 1; o < 32; o <<= 1) {
        const int n = __shfl_up_sync(0xffffffffu, v, o);
        if (lane >= o) v += n;
    }
    const int toff = v - tcnt;
    if (lane == 31) swtot[warp] = v;
    __syncthreads();                                           // (2)
    int wbase = 0;
#pragma unroll
    for (int w = 0; w < 4; w++)
        if (w < warp) wbase += swtot[w];
    int pos = wbase + toff;
#pragma unroll
    for (int x = 0; x < 16; x++) {
        if ((nz >> x) & 1u) {
            slist[pos] = make_float2(__int_as_float(j0 + x), z[x]);
            pos++;
        }
    }
    __syncthreads();                                           // (3)
    if (warp != 0) return;                 // warps 1-3 done

    // ---- warp 0: Michelot on the small smem list (shfl-only) ----
    const int total = swtot[0] + swtot[1] + swtot[2] + swtot[3];
    float tau = tau0;
    int prev = -1;
    for (int it = 0; it < 32; it++) {
        float S = 0.0f, C = 0.0f;
        for (int n = lane; n < total; n += 32) {
            const float y = slist[n].y;
            if (y > tau) { S += y; C += 1.0f; }
        }
#pragma unroll
        for (int o = 16; o > 0; o >>= 1) {
            S += __shfl_xor_sync(0xffffffffu, S, o);
            C += __shfl_xor_sync(0xffffffffu, C, o);
        }
        const int ci = (int)C;             // >=1 always (argmax survives)
        tau = (S - 1.0f) / C;
        if (ci == prev) break;             // support stable -> converged
        prev = ci;
    }

    // ---- final order-preserving compaction + gmem write ----
    float2* lst = g_list + base;
    int opos = 0;
    for (int n0 = 0; n0 < total; n0 += 32) {
        const int n = n0 + lane;
        float2 e; bool keep = false;
        if (n < total) { e = slist[n]; keep = (e.y > tau); }
        const unsigned b = __ballot_sync(0xffffffffu, keep);
        if (keep)
            lst[opos + __popc(b & ((1u << lane) - 1u))] = make_float2(e.x, e.y - tau);
        opos += __popc(b);
    }
    if (lane == 0) g_cnt[ch * L + row] = opos;
}

// ---------------------------------------------------------------------------
// Kernel 2: grouped 3x3 conv from SORTED sparse lists + bias + causal zero.
// One block (256 thr) per (out-row i, group g). All 12 lists staged into
// smem with parallel LDGs; ranges + inner loop read smem only; weights live
// in registers during the entry loop (no LDS on the FMA path).
// ---------------------------------------------------------------------------
__global__ __launch_bounds__(256) void conv_sparse_kernel(const float* __restrict__ weight,
                                                          const float* __restrict__ bias,
                                                          float* __restrict__ out)
{
    __shared__ float  wsm[144];        // [4 oc][4 ic][3][3]
    __shared__ float  bsm[4];
    __shared__ int    scnt_s[12];
    __shared__ float2 sl[12][CAP];
    __shared__ int2   srange[12][8];   // [list p][warp]

    const int i    = blockIdx.x;       // output row
    const int g    = blockIdx.y;       // group
    const int tid  = threadIdx.x;
    const int warp = tid >> 5;
    const int j0   = tid * 8;

    if (tid < 144) wsm[tid] = weight[g * 144 + tid];
    if (tid < 4)   bsm[tid] = bias[g * 4 + tid];
    if (tid >= 160 && tid < 172) {     // counts on a different warp than wsm loads
        const int p   = tid - 160;
        const int icc = p / 3;
        const int dr  = p - icc * 3;
        const int r   = i + dr - 1;
        int c = 0;
        if (r >= 0 && r < L) c = g_cnt[(g * 4 + icc) * L + r];
        scnt_s[p] = c;
    }
    __syncthreads();

    // ---- stage lists into smem (independent parallel LDGs) ----
    for (int idx = tid; idx < 12 * CAP; idx += 256) {
        const int p = idx >> 6;            // idx / CAP
        const int n = idx & (CAP - 1);
        const int c = scnt_s[p];
        if (n < c && c <= CAP) {
            const int icc = p / 3;
            const int dr  = p - icc * 3;
            const int r   = i + dr - 1;
            sl[p][n] = g_list[((size_t)(g * 4 + icc) * L + r) * (size_t)L + n];
        }
    }
    __syncthreads();

    // ---- per-(list,warp) ranges via monotone counting over smem ----
    if (tid < 96) {
        const int p = tid >> 3;
        const int w = tid & 7;
        const int c = scnt_s[p];
        int s = 0, e = 0;
        if (c > 0) {
            const int icc = p / 3;
            const int dr  = p - icc * 3;
            const int r   = i + dr - 1;
            const float2* lp = (c <= CAP) ? &sl[p][0]
                : g_list + ((size_t)(g * 4 + icc) * L + r) * (size_t)L;
            const int lo = w * 256 - 1;
            const int hi = w * 256 + 256;
            for (int n = 0; n < c; n++) {
                const int col = __float_as_int(lp[n].x);   // sorted ascending
                s += (col < lo);
                e += (col <= hi);
            }
        }
        srange[p][w] = make_int2(s, e);
    }
    __syncthreads();

    // ---- threads fully above the diagonal: zero-store and exit ----
    if (j0 > i) {
        const float4 zq = make_float4(0.f, 0.f, 0.f, 0.f);
#pragma unroll
        for (int o = 0; o < 4; o++) {
            float* ob = out + ((size_t)(g * 4 + o) * L + i) * (size_t)L + j0;
            *reinterpret_cast<float4*>(ob)     = zq;
            *reinterpret_cast<float4*>(ob + 4) = zq;
        }
        return;
    }

    float acc[4][8];
#pragma unroll
    for (int o = 0; o < 4; o++)
#pragma unroll
        for (int x = 0; x < 8; x++) acc[o][x] = 0.0f;

#pragma unroll
    for (int p = 0; p < 12; p++) {
        const int icc = p / 3;
        const int dr  = p - icc * 3;
        const int c   = scnt_s[p];
        if (c == 0) continue;                    // covers invalid rows too
        const int2 se = srange[p][warp];
        if (se.x >= se.y) continue;

        // weights for this plane -> registers (no LDS in the entry loop)
        float w0[4], w1[4], w2[4];
#pragma unroll
        for (int o = 0; o < 4; o++) {
            const int wb = ((o * 4 + icc) * 3 + dr) * 3;
            w0[o] = wsm[wb + 0]; w1[o] = wsm[wb + 1]; w2[o] = wsm[wb + 2];
        }

        const int r = i + dr - 1;
        const float2* lp = (c <= CAP) ? &sl[p][0]
            : g_list + ((size_t)(g * 4 + icc) * L + r) * (size_t)L;

        for (int n = se.x; n < se.y; n++) {
            const float2 e = lp[n];
            const int rel = __float_as_int(e.x) - j0 + 1;   // tap center, 0..9 valid
            if ((unsigned)rel > 9u) continue;
            const float v = e.y;
#pragma unroll
            for (int x = 0; x < 8; x++) {
                const int dc = rel - x;
                if ((unsigned)dc < 3u) {
#pragma unroll
                    for (int o = 0; o < 4; o++) {
                        const float ws = (dc == 0) ? w0[o] : ((dc == 1) ? w1[o] : w2[o]);
                        acc[o][x] = fmaf(ws, v, acc[o][x]);
                    }
                }
            }
        }
    }

    // ---- bias + causal mask + dense store ----
#pragma unroll
    for (int o = 0; o < 4; o++) {
        const float b = bsm[o];
        float vv[8];
#pragma unroll
        for (int x = 0; x < 8; x++)
            vv[x] = (j0 + x <= i) ? (acc[o][x] + b) : 0.0f;
        float4 v0, v1;
        v0.x=vv[0]; v0.y=vv[1]; v0.z=vv[2]; v0.w=vv[3];
        v1.x=vv[4]; v1.y=vv[5]; v1.z=vv[6]; v1.w=vv[7];
        float* ob = out + ((size_t)(g * 4 + o) * L + i) * (size_t)L + j0;
        *reinterpret_cast<float4*>(ob)     = v0;
        *reinterpret_cast<float4*>(ob + 4) = v1;
    }
}

// ---------------------------------------------------------------------------
extern "C" void kernel_launch(void* const* d_in, const int* in_sizes, int n_in,
                              void* d_out, int out_size)
{
    const float* scores = (const float*)d_in[0];
    const float* weight = (const float*)d_in[1];
    const float* bias   = (const float*)d_in[2];
    float* out = (float*)d_out;

    sparsemax_kernel<<<dim3(L, C_IN), 128>>>(scores);
    conv_sparse_kernel<<<dim3(L, GROUPS), 256>>>(weight, bias, out);
}

// round 7
// speedup vs baseline: 3.1855x; 3.1855x over previous
#include <cuda_runtime.h>
#include <cstdint>

#define L      2048
#define C_IN   16
#define GROUPS 4
#define NEG_INF -1000000000.0f
#define SLOT   32          // fixed padded slots per (ch,row); overflow -> g_list

// Padded fast-path lists: SLOT entries per (ch,row), column-sorted, padded
// with sentinel col = INT_MAX. Always fully written for every row.
__device__ float2 g_slot[(size_t)C_IN * L * SLOT];
// Full-stride overflow lists (correctness fallback when support > SLOT).
__device__ float2 g_list[(size_t)C_IN * L * L];
__device__ int    g_cnt[C_IN * L];

// ---------------------------------------------------------------------------
// Kernel 1: row-wise sparsemax (causal) -> sorted compressed nonzero list.
// One block (128 thr) per (channel,row); thread t owns cols [16t,16t+16).
// tau0 = rowmax-1 bounds the support; survivors of tau0 are compacted to smem
// (sorted), then WARP 0 ALONE finishes Michelot + the final writes.
// ---------------------------------------------------------------------------
__global__ __launch_bounds__(128) void sparsemax_kernel(const float* __restrict__ scores)
{
    const int row  = blockIdx.x;
    const int ch   = blockIdx.y;
    const int tid  = threadIdx.x;
    const int lane = tid & 31;
    const int warp = tid >> 5;            // 4 warps
    const size_t base = ((size_t)ch * L + row) * (size_t)L;
    const int j0  = tid * 16;
    const int rem = row - j0;             // valid elements: x <= rem

    float z[16];
    if (rem >= 15) {
#pragma unroll
        for (int q = 0; q < 4; q++) {
            const float4 a = *reinterpret_cast<const float4*>(scores + base + j0 + 4 * q);
            z[4*q+0]=a.x; z[4*q+1]=a.y; z[4*q+2]=a.z; z[4*q+3]=a.w;
        }
    } else {
#pragma unroll
        for (int x = 0; x < 16; x++)
            z[x] = (x <= rem) ? scores[base + j0 + x] : NEG_INF;
    }

    __shared__ float  smax[4];
    __shared__ int    swtot[4];
    __shared__ float2 slist[2048];        // survivors of tau0 (capacity-proof)

    // ---- row max ----
    float m = z[0];
#pragma unroll
    for (int k = 1; k < 16; k++) m = fmaxf(m, z[k]);
#pragma unroll
    for (int o = 16; o > 0; o >>= 1) m = fmaxf(m, __shfl_xor_sync(0xffffffffu, m, o));
    if (lane == 0) smax[warp] = m;
    __syncthreads();                                           // (1)
    const float tau0 = fmaxf(fmaxf(smax[0], smax[1]), fmaxf(smax[2], smax[3])) - 1.0f;

    // ---- compact survivors of tau0 into smem, column-sorted ----
    unsigned nz = 0u;
#pragma unroll
    for (int x = 0; x < 16; x++)
        if (z[x] > tau0) nz |= (1u << x);
    const int tcnt = __popc(nz);

    int v = tcnt;                          // warp inclusive scan
#pragma unroll
    for (int o = 1; o < 32; o <<= 1) {
        const int n = __shfl_up_sync(0xffffffffu, v, o);
        if (lane >= o) v += n;
    }
    const int toff = v - tcnt;
    if (lane == 31) swtot[warp] = v;
    __syncthreads();                                           // (2)
    int wbase = 0;
#pragma unroll
    for (int w = 0; w < 4; w++)
        if (w < warp) wbase += swtot[w];
    int pos = wbase + toff;
#pragma unroll
    for (int x = 0; x < 16; x++) {
        if ((nz >> x) & 1u) {
            slist[pos] = make_float2(__int_as_float(j0 + x), z[x]);
            pos++;
        }
    }
    __syncthreads();                                           // (3)
    if (warp != 0) return;                 // warps 1-3 done

    // ---- warp 0: Michelot on the small smem list (shfl-only) ----
    const int total = swtot[0] + swtot[1] + swtot[2] + swtot[3];
    float tau = tau0;
    int prev = -1;
    for (int it = 0; it < 32; it++) {
        float S = 0.0f, C = 0.0f;
        for (int n = lane; n < total; n += 32) {
            const float y = slist[n].y;
            if (y > tau) { S += y; C += 1.0f; }
        }
#pragma unroll
        for (int o = 16; o > 0; o >>= 1) {
            S += __shfl_xor_sync(0xffffffffu, S, o);
            C += __shfl_xor_sync(0xffffffffu, C, o);
        }
        const int ci = (int)C;             // >=1 always (argmax survives)
        tau = (S - 1.0f) / C;
        if (ci == prev) break;             // support stable -> converged
        prev = ci;
    }

    // ---- final order-preserving compaction: slots (+ overflow list) ----
    float2* slot = g_slot + (size_t)(ch * L + row) * SLOT;
    float2* lst  = g_list + base;
    int opos = 0;
    for (int n0 = 0; n0 < total; n0 += 32) {
        const int n = n0 + lane;
        float2 e; bool keep = false;
        if (n < total) { e = slist[n]; keep = (e.y > tau); }
        const unsigned b = __ballot_sync(0xffffffffu, keep);
        if (keep) {
            const int k = opos + __popc(b & ((1u << lane) - 1u));
            const float2 w = make_float2(e.x, e.y - tau);
            if (k < SLOT) slot[k] = w;
            lst[k] = w;                    // overflow-safe full copy (tiny)
        }
        opos += __popc(b);
    }
    // sentinel-pad remaining slots (col = INT_MAX)
    for (int n = opos + lane; n < SLOT; n += 32)
        slot[n] = make_float2(__int_as_float(0x7FFFFFFF), 0.0f);
    if (lane == 0) g_cnt[ch * L + row] = opos;
}

// ---------------------------------------------------------------------------
// Kernel 2: grouped 3x3 conv from SORTED sparse lists + bias + causal zero.
// One block (256 thr) per (out-row i, group g). Warp w covers cols [256w,256w+256).
// 96 threads precompute per-(list,warp) [start,end) ranges with a fully
// UNROLLED 32-slot scan (independent LDGs, sentinel-padded -> no count dep).
// ---------------------------------------------------------------------------
__global__ __launch_bounds__(256) void conv_sparse_kernel(const float* __restrict__ weight,
                                                          const float* __restrict__ bias,
                                                          float* __restrict__ out)
{
    __shared__ float wsm[144];       // [4 oc][4 ic][3][3]
    __shared__ float bsm[4];
    __shared__ int   scnt_s[12];
    __shared__ int2  srange[12][8];  // [list p = icc*3+dr][warp]

    const int i    = blockIdx.x;     // output row
    const int g    = blockIdx.y;     // group
    const int tid  = threadIdx.x;
    const int warp = tid >> 5;
    const int j0   = tid * 8;

    if (tid < 144) wsm[tid] = weight[g * 144 + tid];
    if (tid < 4)   bsm[tid] = bias[g * 4 + tid];

    // ---- per-(list,warp) ranges: unrolled sentinel-safe slot scan ----
    if (tid < 96) {
        const int p   = tid >> 3;          // 0..11
        const int w   = tid & 7;           // warp
        const int icc = p / 3;
        const int dr  = p - icc * 3;
        const int r   = i + dr - 1;
        int s = 0, e = 0, c = 0;
        if (r >= 0 && r < L) {
            const int gc = g * 4 + icc;
            c = g_cnt[gc * L + r];
            const float2* sp = g_slot + (size_t)(gc * L + r) * SLOT;
            const int lo = w * 256 - 1;
            const int hi = w * 256 + 256;
#pragma unroll
            for (int n = 0; n < SLOT; n++) {       // 32 independent LDGs
                const int col = __float_as_int(__ldg(&sp[n].x));
                s += (col < lo);
                e += (col <= hi);
            }
            if (c > SLOT) {                        // rare correctness fallback
                const float2* lst = g_list + ((size_t)gc * L + r) * (size_t)L;
                s = 0; e = 0;
                for (int n = 0; n < c; n++) {
                    const int col = __float_as_int(lst[n].x);
                    s += (col < lo);
                    e += (col <= hi);
                }
            }
        }
        if (w == 0) scnt_s[p] = c;
        srange[p][w] = make_int2(s, e);
    }
    __syncthreads();

    // ---- threads fully above the diagonal: zero-store and exit ----
    if (j0 > i) {
        const float4 zq = make_float4(0.f, 0.f, 0.f, 0.f);
#pragma unroll
        for (int o = 0; o < 4; o++) {
            float* ob = out + ((size_t)(g * 4 + o) * L + i) * (size_t)L + j0;
            *reinterpret_cast<float4*>(ob)     = zq;
            *reinterpret_cast<float4*>(ob + 4) = zq;
        }
        return;
    }

    float acc[4][8];
#pragma unroll
    for (int o = 0; o < 4; o++)
#pragma unroll
        for (int x = 0; x < 8; x++) acc[o][x] = 0.0f;

#pragma unroll
    for (int p = 0; p < 12; p++) {
        const int icc = p / 3;
        const int dr  = p - icc * 3;
        const int r   = i + dr - 1;
        if (r < 0 || r >= L) continue;
        const int2 se = srange[p][warp];
        if (se.x >= se.y) continue;
        const int gc = g * 4 + icc;
        const int c  = scnt_s[p];
        const float2* lp = (c <= SLOT)
            ? g_slot + (size_t)(gc * L + r) * SLOT
            : g_list + ((size_t)gc * L + r) * (size_t)L;
        for (int n = se.x; n < se.y; n++) {      // ~1-2 entries, warp-uniform
            const float2 e = __ldg(&lp[n]);      // broadcast load (L1 hot)
            const int jc = __float_as_int(e.x);
            if (jc < j0 - 1 || jc > j0 + 8) continue;
            const float v = e.y;
#pragma unroll
            for (int x = 0; x < 8; x++) {
                const int dc = jc - j0 - x + 1;  // kernel col tap
                if (dc >= 0 && dc < 3) {
#pragma unroll
                    for (int o = 0; o < 4; o++)
                        acc[o][x] = fmaf(wsm[((o * 4 + icc) * 3 + dr) * 3 + dc], v, acc[o][x]);
                }
            }
        }
    }

    // ---- bias + causal mask + dense store ----
#pragma unroll
    for (int o = 0; o < 4; o++) {
        const float b = bsm[o];
        float vv[8];
#pragma unroll
        for (int x = 0; x < 8; x++)
            vv[x] = (j0 + x <= i) ? (acc[o][x] + b) : 0.0f;
        float4 v0, v1;
        v0.x=vv[0]; v0.y=vv[1]; v0.z=vv[2]; v0.w=vv[3];
        v1.x=vv[4]; v1.y=vv[5]; v1.z=vv[6]; v1.w=vv[7];
        float* ob = out + ((size_t)(g * 4 + o) * L + i) * (size_t)L + j0;
        *reinterpret_cast<float4*>(ob)     = v0;
        *reinterpret_cast<float4*>(ob + 4) = v1;
    }
}

// ---------------------------------------------------------------------------
extern "C" void kernel_launch(void* const* d_in, const int* in_sizes, int n_in,
                              void* d_out, int out_size)
{
    const float* scores = (const float*)d_in[0];
    const float* weight = (const float*)d_in[1];
    const float* bias   = (const float*)d_in[2];
    float* out = (float*)d_out;

    sparsemax_kernel<<<dim3(L, C_IN), 128>>>(scores);
    conv_sparse_kernel<<<dim3(L, GROUPS), 256>>>(weight, bias, out);
}